// round 16
// baseline (speedup 1.0000x reference)
#include <cuda_runtime.h>
#include <cstdint>

// Problem constants (N=32768, D=64, K=64 per reference)
#define NPTS 32768
#define DIM 64
#define NK 64
#define RPT 4                       // rows per thread
#define NTHREADS 128                // 4 warps; warp w owns e-eighths {w, 7-w}
#define ROWS_PER_BLOCK 128          // 32 lanes * RPT
#define NBLOCKS (NPTS / ROWS_PER_BLOCK)   // 256

// Dynamic smem layout (floats)
#define SM_P    0                   // [2][4096] P double buffer
#define SM_X    8192                // [128][65] padded X tile (also absorbs P overread)
#define SM_C    (SM_X + 128 * 65)   // [64] per-cluster constants
#define SM_SDB  (SM_C + 64)         // [64] stick-breaking terms
#define SM_SQP  (SM_SDB + 64)       // [2][4][128] per-warp sq partials
#define SM_TOTF (SM_SQP + 2 * 4 * 128)
#define SMEM_BYTES (SM_TOTF * 4)

// Scratch (allocation-free rule: __device__ globals)
__device__ __align__(16) float d_negmuP[NK * DIM];  // -(means_k @ P_k), [K,D]
__device__ float d_Cpart[NK];
__device__ float d_sdb[NK];

// ---------------------------------------------------------------------------
static __device__ __forceinline__ double safe_log(double v) {
    v = fabs(v);
    if (v < 1e-300) v = 1e-300;
    return log(v);
}

static __device__ __forceinline__ double digamma_d(double x) {
    if (!(x > 1e-6)) x = 1e-6;
    double r = 0.0;
    const double m = (x < 6.0) ? ceil(6.0 - x) : 0.0;   // <= 6 for x >= 0.5
#pragma unroll
    for (int j = 0; j < 6; ++j)
        if ((double)j < m) r -= 1.0 / (x + (double)j);
    x += m;
    const double inv  = 1.0 / x;
    const double inv2 = inv * inv;
    const double s = inv2 * (1.0 / 12.0
                   - inv2 * (1.0 / 120.0
                   - inv2 * (1.0 / 252.0
                   - inv2 * (1.0 / 240.0))));
    return r + log(x) - 0.5 * inv - s;
}

// ---------------------------------------------------------------------------
// Prep: 64 blocks (cluster k) x 64 threads (dimension i).
// ---------------------------------------------------------------------------
__global__ void bgm_prep_a(const float* __restrict__ means,
                           const float* __restrict__ P,
                           const float* __restrict__ wc,
                           const float* __restrict__ v64a,
                           const float* __restrict__ v64b) {
    const int k = blockIdx.x;
    const int i = threadIdx.x;
    __shared__ double sd[NK];

    const bool a_is_dof = (v64a[0] > 32.0f);   // dof in [65,114], mp in (0.5,10]
    const float* __restrict__ dof = a_is_dof ? v64a : v64b;
    const float* __restrict__ mp  = a_is_dof ? v64b : v64a;

    const double dofk = (double)dof[k];

    const double t  = digamma_d(0.5 * (dofk - (double)i));
    const double lg = safe_log((double)P[k * DIM * DIM + i * DIM + i]);
    sd[i] = lg + 0.5 * t;
    __syncthreads();

    {   // negmuP column i
        float s = 0.0f;
        for (int d = 0; d < DIM; ++d)
            s = fmaf(means[k * DIM + d], P[k * DIM * DIM + d * DIM + i], s);
        d_negmuP[k * DIM + i] = -s;
    }

    for (int off = 32; off > 0; off >>= 1) {
        if (i < off) sd[i] += sd[i + off];
        __syncthreads();
    }

    if (i == 0) {
        double mpk = (double)mp[k];
        if (!(mpk > 1e-6)) mpk = 1e-6;
        const double a  = (double)wc[k];
        const double b  = (double)wc[NK + k];
        const double ds = digamma_d(a + b);
        const double dga = digamma_d(a);
        const double dgb = digamma_d(b);
        double C = sd[0]
                 + 0.5 * (double)DIM * 0.69314718055994530942
                 - 0.5 * (double)DIM * 1.8378770664093454836
                 - 0.5 * (double)DIM * safe_log(dofk)
                 - 0.5 * (double)DIM / mpk
                 + dga - ds;
        d_Cpart[k] = (float)C;
        d_sdb[k]   = (float)(dgb - ds);
    }
}

// ---------------------------------------------------------------------------
// Packed f32x2 helpers
// ---------------------------------------------------------------------------
static __device__ __forceinline__ unsigned long long ff2(
    unsigned long long a, unsigned long long b, unsigned long long c) {
    unsigned long long d;
    asm("fma.rn.f32x2 %0, %1, %2, %3;" : "=l"(d) : "l"(a), "l"(b), "l"(c));
    return d;
}
static __device__ __forceinline__ unsigned long long fadd2(
    unsigned long long a, unsigned long long b) {
    unsigned long long d;
    asm("add.rn.f32x2 %0, %1, %2;" : "=l"(d) : "l"(a), "l"(b));
    return d;
}
static __device__ __forceinline__ unsigned long long pack2(float x) {
    unsigned long long d;
    asm("mov.b64 %0, {%1, %1};" : "=l"(d) : "f"(x));
    return d;
}
static __device__ __forceinline__ void unpack2(unsigned long long v, float& lo, float& hi) {
    asm("mov.b64 {%0, %1}, %2;" : "=f"(lo), "=f"(hi) : "l"(v));
}

// cp.async 16B helpers
static __device__ __forceinline__ void cp16(uint32_t smem_addr, const void* gptr) {
    asm volatile("cp.async.cg.shared.global [%0], [%1], 16;" :: "r"(smem_addr), "l"(gptr));
}
static __device__ __forceinline__ void cp_commit() {
    asm volatile("cp.async.commit_group;");
}
template <int N>
static __device__ __forceinline__ void cp_wait() {
    asm volatile("cp.async.wait_group %0;" :: "n"(N));
}

// ---------------------------------------------------------------------------
// Main kernel: 256 blocks x 128 threads (4 warps), 128 rows/block, R=4.
// e-EIGHTH SPLIT: warp w computes e-eighths {w, 7-w} (d-work 72, balanced;
// triangular bound dmax = 8*(e8+1) — bit-exact zero skip).
// d-loop SOFTWARE-PIPELINED depth 1: P(d+1) and packed X(d+1) prefetched
// into registers before d's 16 FFMA2s. P row stride = 64 floats = 16
// ulonglong2 — hence the `<< 4` (R15's bug was `<< 3` = half a row).
// The d+1==dmax overread stays inside allocated smem and is discarded.
// Per-(row,k) sq = 4 warp partials merged 1-k-deep on the double-buffer
// barriers; warp0 owns argmax (strict >, first-max). OUTPUT: float32.
// ---------------------------------------------------------------------------
__global__ __launch_bounds__(NTHREADS) void bgm_argmax_kernel(
    const float* __restrict__ X,
    const float* __restrict__ P,
    float* __restrict__ out) {

    extern __shared__ __align__(16) float smem[];
    float* __restrict__ Psm = smem + SM_P;
    float* __restrict__ Xsm = smem + SM_X;
    float* __restrict__ Csm = smem + SM_C;
    float* __restrict__ Sdb = smem + SM_SDB;
    float* __restrict__ SqP = smem + SM_SQP;   // [buf][warp][row]

    const int tid  = threadIdx.x;
    const int wid  = tid >> 5;
    const int lane = tid & 31;
    const int row0 = blockIdx.x * ROWS_PER_BLOCK;

    // Stage X tile: 128 rows -> 2048 float4, 16 per thread (padded rows of 65).
    {
        const float4* __restrict__ Xg =
            reinterpret_cast<const float4*>(X + row0 * DIM);
        for (int i = tid; i < ROWS_PER_BLOCK * (DIM / 4); i += NTHREADS) {
            const float4 v = Xg[i];
            const int r = i >> 4;
            const int c = (i & 15) << 2;
            float* dst = &Xsm[r * 65 + c];
            dst[0] = v.x; dst[1] = v.y; dst[2] = v.z; dst[3] = v.w;
        }
    }
    if (tid < NK) Sdb[tid] = d_sdb[tid];
    __syncthreads();
    if (tid < NK) {   // stick-breaking exclusive cumsum (sequential fp32 order)
        float pre = 0.0f;
        for (int j = 0; j < tid; ++j) pre += Sdb[j];
        Csm[tid] = d_Cpart[tid] + pre;
    }

    // Prologue: stage P_0 into buffer 0 (1024 float4 -> 8 per thread)
    {
        const float4* src = reinterpret_cast<const float4*>(P);
        const uint32_t dst = (uint32_t)__cvta_generic_to_shared(&Psm[0]);
#pragma unroll
        for (int j = 0; j < 8; ++j)
            cp16(dst + (tid + j * NTHREADS) * 16, src + tid + j * NTHREADS);
        cp_commit();
    }

    const int e8A = wid;        // eighths {wid, 7-wid}: d-work 8(w+1)+8(8-w)=72
    const int e8B = 7 - wid;

    int xb[RPT];
#pragma unroll
    for (int r = 0; r < RPT; ++r) xb[r] = (lane + 32 * r) * 65;

    float best[RPT], argf[RPT];
#pragma unroll
    for (int r = 0; r < RPT; ++r) { best[r] = __int_as_float(0xff800000u); argf[r] = 0.0f; }

    const ulonglong2* __restrict__ nmAll =
        reinterpret_cast<const ulonglong2*>(d_negmuP);

    for (int k = 0; k < NK; ++k) {
        __syncthreads();   // (a) prev buffer free; all warps' k-1 partials visible

        // Warp0: merge 4 partials for k-1 and update argmax.
        if (wid == 0 && k > 0) {
            const float* pb = SqP + ((k - 1) & 1) * (4 * ROWS_PER_BLOCK);
            const float Ck = Csm[k - 1];
#pragma unroll
            for (int r = 0; r < RPT; ++r) {
                const int row = lane + 32 * r;
                const float s = (pb[row] + pb[ROWS_PER_BLOCK + row])
                              + (pb[2 * ROWS_PER_BLOCK + row] + pb[3 * ROWS_PER_BLOCK + row]);
                const float w = fmaf(-0.5f, s, Ck);
                if (w > best[r]) { best[r] = w; argf[r] = (float)(k - 1); }
            }
        }

        if (k + 1 < NK) {
            const float4* src = reinterpret_cast<const float4*>(P + (k + 1) * DIM * DIM);
            const uint32_t dst = (uint32_t)__cvta_generic_to_shared(
                &Psm[((k + 1) & 1) * DIM * DIM]);
#pragma unroll
            for (int j = 0; j < 8; ++j)
                cp16(dst + (tid + j * NTHREADS) * 16, src + tid + j * NTHREADS);
            cp_commit();
            cp_wait<1>();   // P_k complete; P_{k+1} in flight
        } else {
            cp_wait<0>();
        }
        __syncthreads();    // (b) P_k visible to all warps

        const float* __restrict__ Pk = &Psm[(k & 1) * DIM * DIM];
        unsigned long long srow[RPT];
#pragma unroll
        for (int r = 0; r < RPT; ++r) srow[r] = 0ULL;

#pragma unroll
        for (int h = 0; h < 2; ++h) {
            const int e8   = (h == 0) ? e8A : e8B;
            const int dmax = 8 * (e8 + 1);       // triangular bound
            const int eoff = e8 << 3;            // e-offset in floats

            unsigned long long acc[RPT][4];
#pragma unroll
            for (int r = 0; r < RPT; ++r)
#pragma unroll
                for (int j = 0; j < 4; ++j) acc[r][j] = 0ULL;

            // Software pipeline: prefetch d=0 operands.
            // P row stride: 64 floats = 16 ulonglong2 (hence << 4 below).
            const ulonglong2* __restrict__ prQ =
                reinterpret_cast<const ulonglong2*>(Pk + eoff);
            ulonglong2 pn0 = prQ[0];
            ulonglong2 pn1 = prQ[1];
            unsigned long long xn[RPT];
#pragma unroll
            for (int r = 0; r < RPT; ++r) xn[r] = pack2(Xsm[xb[r]]);

#pragma unroll 4
            for (int d = 0; d < dmax; ++d) {
                const ulonglong2 p0 = pn0;
                const ulonglong2 p1 = pn1;
                unsigned long long xc[RPT];
#pragma unroll
                for (int r = 0; r < RPT; ++r) xc[r] = xn[r];

                // Prefetch d+1 (overread at d+1==dmax stays in smem; discarded).
                const ulonglong2* __restrict__ pnext = prQ + ((d + 1) << 4);
                pn0 = pnext[0];
                pn1 = pnext[1];
#pragma unroll
                for (int r = 0; r < RPT; ++r) xn[r] = pack2(Xsm[xb[r] + d + 1]);

#pragma unroll
                for (int r = 0; r < RPT; ++r) {
                    acc[r][0] = ff2(xc[r], p0.x, acc[r][0]);
                    acc[r][1] = ff2(xc[r], p0.y, acc[r][1]);
                    acc[r][2] = ff2(xc[r], p1.x, acc[r][2]);
                    acc[r][3] = ff2(xc[r], p1.y, acc[r][3]);
                }
            }

            // Eighth epilogue: srow += (acc + negmuP_eighth)^2
            const ulonglong2* __restrict__ nm = nmAll + (k << 4) + (e8 << 1);
            const ulonglong2 m0 = nm[0];
            const ulonglong2 m1 = nm[1];
#pragma unroll
            for (int r = 0; r < RPT; ++r) {
                const unsigned long long ea = fadd2(acc[r][0], m0.x);
                const unsigned long long eb = fadd2(acc[r][1], m0.y);
                const unsigned long long ec = fadd2(acc[r][2], m1.x);
                const unsigned long long ed = fadd2(acc[r][3], m1.y);
                srow[r] = ff2(ea, ea, srow[r]);
                srow[r] = ff2(eb, eb, srow[r]);
                srow[r] = ff2(ec, ec, srow[r]);
                srow[r] = ff2(ed, ed, srow[r]);
            }
        }

        // Publish this warp's partials for k.
        float* sp = SqP + (k & 1) * (4 * ROWS_PER_BLOCK) + wid * ROWS_PER_BLOCK;
#pragma unroll
        for (int r = 0; r < RPT; ++r) {
            float lo, hi;
            unpack2(srow[r], lo, hi);
            sp[lane + 32 * r] = lo + hi;
        }
    }

    __syncthreads();   // k=63 partials visible
    if (wid == 0) {
        const float* pb = SqP + ((NK - 1) & 1) * (4 * ROWS_PER_BLOCK);
        const float Ck = Csm[NK - 1];
#pragma unroll
        for (int r = 0; r < RPT; ++r) {
            const int row = lane + 32 * r;
            const float s = (pb[row] + pb[ROWS_PER_BLOCK + row])
                          + (pb[2 * ROWS_PER_BLOCK + row] + pb[3 * ROWS_PER_BLOCK + row]);
            const float w = fmaf(-0.5f, s, Ck);
            if (w > best[r]) { best[r] = w; argf[r] = (float)(NK - 1); }
            out[row0 + row] = argf[r];
        }
    }
}

// ---------------------------------------------------------------------------
// Launch. Inputs identified by ELEMENT COUNT; dof/mp disambiguated on device.
// Output: float32 index values [N].
// ---------------------------------------------------------------------------
extern "C" void kernel_launch(void* const* d_in, const int* in_sizes, int n_in,
                              void* d_out, int out_size) {
    (void)out_size;
    const float* X     = nullptr;
    const float* means = nullptr;
    const float* P     = nullptr;
    const float* wc    = nullptr;
    const float* v64a  = nullptr;
    const float* v64b  = nullptr;

    for (int i = 0; i < n_in; ++i) {
        const float* p = (const float*)d_in[i];
        switch (in_sizes[i]) {
            case 2097152: X = p; break;
            case 262144:  P = p; break;
            case 4096:    means = p; break;
            case 128:     wc = p; break;
            case 64:      if (!v64a) v64a = p; else v64b = p; break;
            default: break;
        }
    }
    if (!v64b) v64b = v64a;  // defensive
    float* out = (float*)d_out;

    static bool attr_set = false;
    if (!attr_set) {
        cudaFuncSetAttribute(bgm_argmax_kernel,
                             cudaFuncAttributeMaxDynamicSharedMemorySize,
                             SMEM_BYTES);
        attr_set = true;
    }

    bgm_prep_a<<<NK, DIM>>>(means, P, wc, v64a, v64b);
    bgm_argmax_kernel<<<NBLOCKS, NTHREADS, SMEM_BYTES>>>(X, P, out);
}

// round 17
// speedup vs baseline: 1.0756x; 1.0756x over previous
#include <cuda_runtime.h>
#include <cstdint>

// Problem constants (N=32768, D=64, K=64 per reference)
#define NPTS 32768
#define DIM 64
#define NK 64
#define RPT 4                       // rows per thread
#define NTHREADS 128                // 4 warps; warp w owns e-eighths {w, 7-w}
#define ROWS_PER_BLOCK 128          // 32 lanes * RPT
#define NTILES (NPTS / ROWS_PER_BLOCK)    // 256 row tiles
#define KSPLIT 2                    // k halves
#define KPER (NK / KSPLIT)          // 32 clusters per block
#define NBLOCKS (NTILES * KSPLIT)   // 512

// Dynamic smem layout (floats)
#define SM_P    0                   // [2][4096] P double buffer
#define SM_X    8192                // [128][65] padded X tile
#define SM_C    (SM_X + 128 * 65)   // [64] per-cluster constants
#define SM_SDB  (SM_C + 64)         // [64] stick-breaking terms
#define SM_SQP  (SM_SDB + 64)       // [2][4][128] per-warp sq partials
#define SM_TOTF (SM_SQP + 2 * 4 * 128)
#define SMEM_BYTES (SM_TOTF * 4)

// Scratch (allocation-free rule: __device__ globals)
__device__ __align__(16) float d_negmuP[NK * DIM];  // -(means_k @ P_k), [K,D]
__device__ float d_Cpart[NK];
__device__ float d_sdb[NK];
__device__ float d_bestPart[KSPLIT][NPTS];          // per-k-half best wlp
__device__ int   d_argPart[KSPLIT][NPTS];           // per-k-half argmax

// ---------------------------------------------------------------------------
static __device__ __forceinline__ double safe_log(double v) {
    v = fabs(v);
    if (v < 1e-300) v = 1e-300;
    return log(v);
}

static __device__ __forceinline__ double digamma_d(double x) {
    if (!(x > 1e-6)) x = 1e-6;
    double r = 0.0;
    const double m = (x < 6.0) ? ceil(6.0 - x) : 0.0;   // <= 6 for x >= 0.5
#pragma unroll
    for (int j = 0; j < 6; ++j)
        if ((double)j < m) r -= 1.0 / (x + (double)j);
    x += m;
    const double inv  = 1.0 / x;
    const double inv2 = inv * inv;
    const double s = inv2 * (1.0 / 12.0
                   - inv2 * (1.0 / 120.0
                   - inv2 * (1.0 / 252.0
                   - inv2 * (1.0 / 240.0))));
    return r + log(x) - 0.5 * inv - s;
}

// ---------------------------------------------------------------------------
// Prep: 64 blocks (cluster k) x 64 threads (dimension i).
// ---------------------------------------------------------------------------
__global__ void bgm_prep_a(const float* __restrict__ means,
                           const float* __restrict__ P,
                           const float* __restrict__ wc,
                           const float* __restrict__ v64a,
                           const float* __restrict__ v64b) {
    const int k = blockIdx.x;
    const int i = threadIdx.x;
    __shared__ double sd[NK];

    const bool a_is_dof = (v64a[0] > 32.0f);   // dof in [65,114], mp in (0.5,10]
    const float* __restrict__ dof = a_is_dof ? v64a : v64b;
    const float* __restrict__ mp  = a_is_dof ? v64b : v64a;

    const double dofk = (double)dof[k];

    const double t  = digamma_d(0.5 * (dofk - (double)i));
    const double lg = safe_log((double)P[k * DIM * DIM + i * DIM + i]);
    sd[i] = lg + 0.5 * t;
    __syncthreads();

    {   // negmuP column i
        float s = 0.0f;
        for (int d = 0; d < DIM; ++d)
            s = fmaf(means[k * DIM + d], P[k * DIM * DIM + d * DIM + i], s);
        d_negmuP[k * DIM + i] = -s;
    }

    for (int off = 32; off > 0; off >>= 1) {
        if (i < off) sd[i] += sd[i + off];
        __syncthreads();
    }

    if (i == 0) {
        double mpk = (double)mp[k];
        if (!(mpk > 1e-6)) mpk = 1e-6;
        const double a  = (double)wc[k];
        const double b  = (double)wc[NK + k];
        const double ds = digamma_d(a + b);
        const double dga = digamma_d(a);
        const double dgb = digamma_d(b);
        double C = sd[0]
                 + 0.5 * (double)DIM * 0.69314718055994530942
                 - 0.5 * (double)DIM * 1.8378770664093454836
                 - 0.5 * (double)DIM * safe_log(dofk)
                 - 0.5 * (double)DIM / mpk
                 + dga - ds;
        d_Cpart[k] = (float)C;
        d_sdb[k]   = (float)(dgb - ds);
    }
}

// ---------------------------------------------------------------------------
// Packed f32x2 helpers
// ---------------------------------------------------------------------------
static __device__ __forceinline__ unsigned long long ff2(
    unsigned long long a, unsigned long long b, unsigned long long c) {
    unsigned long long d;
    asm("fma.rn.f32x2 %0, %1, %2, %3;" : "=l"(d) : "l"(a), "l"(b), "l"(c));
    return d;
}
static __device__ __forceinline__ unsigned long long fadd2(
    unsigned long long a, unsigned long long b) {
    unsigned long long d;
    asm("add.rn.f32x2 %0, %1, %2;" : "=l"(d) : "l"(a), "l"(b));
    return d;
}
static __device__ __forceinline__ unsigned long long pack2(float x) {
    unsigned long long d;
    asm("mov.b64 %0, {%1, %1};" : "=l"(d) : "f"(x));
    return d;
}
static __device__ __forceinline__ void unpack2(unsigned long long v, float& lo, float& hi) {
    asm("mov.b64 {%0, %1}, %2;" : "=f"(lo), "=f"(hi) : "l"(v));
}

// cp.async 16B helpers
static __device__ __forceinline__ void cp16(uint32_t smem_addr, const void* gptr) {
    asm volatile("cp.async.cg.shared.global [%0], [%1], 16;" :: "r"(smem_addr), "l"(gptr));
}
static __device__ __forceinline__ void cp_commit() {
    asm volatile("cp.async.commit_group;");
}
template <int N>
static __device__ __forceinline__ void cp_wait() {
    asm volatile("cp.async.wait_group %0;" :: "n"(N));
}

// ---------------------------------------------------------------------------
// Main kernel: 512 blocks = 256 row-tiles x 2 k-halves; 128 threads (4 warps),
// 128 rows/block, R=4, 32 clusters per block.
// e-EIGHTH SPLIT: warp w computes e-eighths {w, 7-w} (d-work 72, balanced;
// triangular bound dmax = 8*(e8+1) — bit-exact zero skip). R14's proven
// d-loop body (no register prefetch — twice shown not to help).
// Per-(row,k) sq = 4 warp partials merged 1-k-deep on the double-buffer
// barriers; warp0 owns the k-half argmax (strict >, first-max) and writes
// it to global scratch. A tiny merge kernel combines the two halves.
// ---------------------------------------------------------------------------
__global__ __launch_bounds__(NTHREADS) void bgm_argmax_kernel(
    const float* __restrict__ X,
    const float* __restrict__ P) {

    extern __shared__ __align__(16) float smem[];
    float* __restrict__ Psm = smem + SM_P;
    float* __restrict__ Xsm = smem + SM_X;
    float* __restrict__ Csm = smem + SM_C;
    float* __restrict__ Sdb = smem + SM_SDB;
    float* __restrict__ SqP = smem + SM_SQP;   // [buf][warp][row]

    const int tid    = threadIdx.x;
    const int wid    = tid >> 5;
    const int lane   = tid & 31;
    const int tile   = blockIdx.x % NTILES;
    const int ksp    = blockIdx.x / NTILES;    // 0 or 1
    const int kbase  = ksp * KPER;
    const int row0   = tile * ROWS_PER_BLOCK;

    // Stage X tile: 128 rows -> 2048 float4, 16 per thread (padded rows of 65).
    {
        const float4* __restrict__ Xg =
            reinterpret_cast<const float4*>(X + row0 * DIM);
        for (int i = tid; i < ROWS_PER_BLOCK * (DIM / 4); i += NTHREADS) {
            const float4 v = Xg[i];
            const int r = i >> 4;
            const int c = (i & 15) << 2;
            float* dst = &Xsm[r * 65 + c];
            dst[0] = v.x; dst[1] = v.y; dst[2] = v.z; dst[3] = v.w;
        }
    }
    if (tid < NK) Sdb[tid] = d_sdb[tid];
    __syncthreads();
    if (tid < NK) {   // stick-breaking exclusive cumsum (sequential fp32 order)
        float pre = 0.0f;
        for (int j = 0; j < tid; ++j) pre += Sdb[j];
        Csm[tid] = d_Cpart[tid] + pre;
    }

    // Prologue: stage P_{kbase} into buffer 0 (1024 float4 -> 8 per thread)
    {
        const float4* src = reinterpret_cast<const float4*>(P + kbase * DIM * DIM);
        const uint32_t dst = (uint32_t)__cvta_generic_to_shared(&Psm[0]);
#pragma unroll
        for (int j = 0; j < 8; ++j)
            cp16(dst + (tid + j * NTHREADS) * 16, src + tid + j * NTHREADS);
        cp_commit();
    }

    const int e8A = wid;        // eighths {wid, 7-wid}: d-work 8(w+1)+8(8-w)=72
    const int e8B = 7 - wid;

    int xb[RPT];
#pragma unroll
    for (int r = 0; r < RPT; ++r) xb[r] = (lane + 32 * r) * 65;

    float best[RPT];
    int   argi[RPT];
#pragma unroll
    for (int r = 0; r < RPT; ++r) { best[r] = __int_as_float(0xff800000u); argi[r] = kbase; }

    const ulonglong2* __restrict__ nmAll =
        reinterpret_cast<const ulonglong2*>(d_negmuP);

    for (int kk = 0; kk < KPER; ++kk) {
        const int k = kbase + kk;
        __syncthreads();   // (a) prev buffer free; all warps' kk-1 partials visible

        // Warp0: merge 4 partials for kk-1 and update argmax.
        if (wid == 0 && kk > 0) {
            const float* pb = SqP + ((kk - 1) & 1) * (4 * ROWS_PER_BLOCK);
            const float Ck = Csm[k - 1];
#pragma unroll
            for (int r = 0; r < RPT; ++r) {
                const int row = lane + 32 * r;
                const float s = (pb[row] + pb[ROWS_PER_BLOCK + row])
                              + (pb[2 * ROWS_PER_BLOCK + row] + pb[3 * ROWS_PER_BLOCK + row]);
                const float w = fmaf(-0.5f, s, Ck);
                if (w > best[r]) { best[r] = w; argi[r] = k - 1; }
            }
        }

        if (kk + 1 < KPER) {
            const float4* src = reinterpret_cast<const float4*>(P + (k + 1) * DIM * DIM);
            const uint32_t dst = (uint32_t)__cvta_generic_to_shared(
                &Psm[((kk + 1) & 1) * DIM * DIM]);
#pragma unroll
            for (int j = 0; j < 8; ++j)
                cp16(dst + (tid + j * NTHREADS) * 16, src + tid + j * NTHREADS);
            cp_commit();
            cp_wait<1>();   // P_k complete; P_{k+1} in flight
        } else {
            cp_wait<0>();
        }
        __syncthreads();    // (b) P_k visible to all warps

        const float* __restrict__ Pk = &Psm[(kk & 1) * DIM * DIM];
        unsigned long long srow[RPT];
#pragma unroll
        for (int r = 0; r < RPT; ++r) srow[r] = 0ULL;

#pragma unroll
        for (int h = 0; h < 2; ++h) {
            const int e8   = (h == 0) ? e8A : e8B;
            const int dmax = 8 * (e8 + 1);       // triangular bound
            const int eoff = e8 << 3;            // e-offset in floats

            unsigned long long acc[RPT][4];
#pragma unroll
            for (int r = 0; r < RPT; ++r)
#pragma unroll
                for (int j = 0; j < 4; ++j) acc[r][j] = 0ULL;

#pragma unroll 4
            for (int d = 0; d < dmax; ++d) {
                const ulonglong2* __restrict__ pr =
                    reinterpret_cast<const ulonglong2*>(Pk + (d << 6) + eoff);
                const ulonglong2 p0 = pr[0];     // 2 uniform LDS.128 = 4 f32x2
                const ulonglong2 p1 = pr[1];
#pragma unroll
                for (int r = 0; r < RPT; ++r) {
                    const unsigned long long xr = pack2(Xsm[xb[r] + d]);
                    acc[r][0] = ff2(xr, p0.x, acc[r][0]);
                    acc[r][1] = ff2(xr, p0.y, acc[r][1]);
                    acc[r][2] = ff2(xr, p1.x, acc[r][2]);
                    acc[r][3] = ff2(xr, p1.y, acc[r][3]);
                }
            }

            // Eighth epilogue: srow += (acc + negmuP_eighth)^2
            const ulonglong2* __restrict__ nm = nmAll + (k << 4) + (e8 << 1);
            const ulonglong2 m0 = nm[0];
            const ulonglong2 m1 = nm[1];
#pragma unroll
            for (int r = 0; r < RPT; ++r) {
                const unsigned long long ea = fadd2(acc[r][0], m0.x);
                const unsigned long long eb = fadd2(acc[r][1], m0.y);
                const unsigned long long ec = fadd2(acc[r][2], m1.x);
                const unsigned long long ed = fadd2(acc[r][3], m1.y);
                srow[r] = ff2(ea, ea, srow[r]);
                srow[r] = ff2(eb, eb, srow[r]);
                srow[r] = ff2(ec, ec, srow[r]);
                srow[r] = ff2(ed, ed, srow[r]);
            }
        }

        // Publish this warp's partials for kk.
        float* sp = SqP + (kk & 1) * (4 * ROWS_PER_BLOCK) + wid * ROWS_PER_BLOCK;
#pragma unroll
        for (int r = 0; r < RPT; ++r) {
            float lo, hi;
            unpack2(srow[r], lo, hi);
            sp[lane + 32 * r] = lo + hi;
        }
    }

    __syncthreads();   // kk=KPER-1 partials visible
    if (wid == 0) {
        const float* pb = SqP + ((KPER - 1) & 1) * (4 * ROWS_PER_BLOCK);
        const int klast = kbase + KPER - 1;
        const float Ck = Csm[klast];
#pragma unroll
        for (int r = 0; r < RPT; ++r) {
            const int row = lane + 32 * r;
            const float s = (pb[row] + pb[ROWS_PER_BLOCK + row])
                          + (pb[2 * ROWS_PER_BLOCK + row] + pb[3 * ROWS_PER_BLOCK + row]);
            const float w = fmaf(-0.5f, s, Ck);
            if (w > best[r]) { best[r] = w; argi[r] = klast; }
            d_bestPart[ksp][row0 + row] = best[r];
            d_argPart[ksp][row0 + row]  = argi[r];
        }
    }
}

// ---------------------------------------------------------------------------
// Merge kernel: combine the two k-halves. Lower-k half wins ties (strict >)
// -> jnp.argmax first-max semantics. OUTPUT: float32 index values.
// ---------------------------------------------------------------------------
__global__ void bgm_merge_kernel(float* __restrict__ out) {
    const int row = blockIdx.x * blockDim.x + threadIdx.x;
    const float b0 = d_bestPart[0][row];
    const float b1 = d_bestPart[1][row];
    int a = d_argPart[0][row];
    if (b1 > b0) a = d_argPart[1][row];
    out[row] = (float)a;
}

// ---------------------------------------------------------------------------
// Launch. Inputs identified by ELEMENT COUNT; dof/mp disambiguated on device.
// Output: float32 index values [N].
// ---------------------------------------------------------------------------
extern "C" void kernel_launch(void* const* d_in, const int* in_sizes, int n_in,
                              void* d_out, int out_size) {
    (void)out_size;
    const float* X     = nullptr;
    const float* means = nullptr;
    const float* P     = nullptr;
    const float* wc    = nullptr;
    const float* v64a  = nullptr;
    const float* v64b  = nullptr;

    for (int i = 0; i < n_in; ++i) {
        const float* p = (const float*)d_in[i];
        switch (in_sizes[i]) {
            case 2097152: X = p; break;
            case 262144:  P = p; break;
            case 4096:    means = p; break;
            case 128:     wc = p; break;
            case 64:      if (!v64a) v64a = p; else v64b = p; break;
            default: break;
        }
    }
    if (!v64b) v64b = v64a;  // defensive
    float* out = (float*)d_out;

    static bool attr_set = false;
    if (!attr_set) {
        cudaFuncSetAttribute(bgm_argmax_kernel,
                             cudaFuncAttributeMaxDynamicSharedMemorySize,
                             SMEM_BYTES);
        attr_set = true;
    }

    bgm_prep_a<<<NK, DIM>>>(means, P, wc, v64a, v64b);
    bgm_argmax_kernel<<<NBLOCKS, NTHREADS, SMEM_BYTES>>>(X, P);
    bgm_merge_kernel<<<NPTS / 256, 256>>>(out);
}